// round 2
// baseline (speedup 1.0000x reference)
#include <cuda_runtime.h>
#include <cstdint>

// ---------------------------------------------------------------------------
// GATNet: 2-layer multi-head graph attention, fp32 CUDA-core baseline.
//   B=16, N=1024, CIN=64, D=128, H=8, COUT=64
// Pipeline:
//   feat1:  H1[h][b*N+n][128] = flow_x[b*N+n][64] @ Wh[h]            (8 GEMMs)
//   attn1:  per (h,b): flash-attention with graph mask, epilogue adds bh[h],
//           leaky-relu, writes X2[b*N+n][h*128+j]  (the concat layout)
//   feat2:  H2[b*N+n][64] = X2 @ W_out
//   attn2:  per b: flash-attention, epilogue adds b_out, leaky-relu -> d_out
// ---------------------------------------------------------------------------

#define LOG2E 1.4426950408889634f

static const int NV   = 1024;   // nodes
static const int BV   = 16;     // batch
static const int DH   = 128;    // per-head hidden
static const int NHV  = 8;      // heads
static const int COUT = 64;

// scratch (no cudaMalloc allowed)
__device__ float g_H1[(size_t)NHV * BV * NV * DH];      // 67 MB
__device__ float g_X2[(size_t)BV * NV * (NHV * DH)];    // 64 MB
__device__ float g_H2[(size_t)BV * NV * COUT];          // 4 MB

// ---------------------------------------------------------------------------
// feat1: per-head feature GEMM. M=16384 rows, K=64, Ncols=128.
// Block: 256 threads, tile 128 rows x 128 cols, 8x8 microtile.
// ---------------------------------------------------------------------------
__global__ __launch_bounds__(256, 1)
void feat1_kernel(const float* __restrict__ x, const float* __restrict__ Wh,
                  float* __restrict__ H1)
{
    const int BMP = 132;
    extern __shared__ float sm[];
    float* Xs = sm;                // [64][132]  (k-major, transposed x tile)
    float* Ws = sm + 64 * BMP;     // [64][132]  (k-major, natural Wh layout)

    int tid = threadIdx.x, tx = tid & 15, ty = tid >> 4;
    int h = blockIdx.y;
    int rowbase = blockIdx.x * 128;
    const float* W = Wh + (size_t)h * 64 * 128;

    // load x tile transposed: Xs[k][row]
    for (int idx = tid; idx < 128 * 16; idx += 256) {
        int row = idx >> 4, c4 = idx & 15;
        float4 v = *(const float4*)(x + (size_t)(rowbase + row) * 64 + c4 * 4);
        Xs[(c4 * 4 + 0) * BMP + row] = v.x;
        Xs[(c4 * 4 + 1) * BMP + row] = v.y;
        Xs[(c4 * 4 + 2) * BMP + row] = v.z;
        Xs[(c4 * 4 + 3) * BMP + row] = v.w;
    }
    // load W straight: Ws[k][d]
    for (int idx = tid; idx < 64 * 32; idx += 256) {
        int k = idx >> 5, c4 = idx & 31;
        *(float4*)&Ws[k * BMP + c4 * 4] = *(const float4*)(W + k * 128 + c4 * 4);
    }
    __syncthreads();

    float acc[8][8];
#pragma unroll
    for (int r = 0; r < 8; r++)
#pragma unroll
        for (int u = 0; u < 8; u++) acc[r][u] = 0.0f;

#pragma unroll 4
    for (int k = 0; k < 64; k++) {
        float4 a0 = *(const float4*)&Xs[k * BMP + ty * 8];
        float4 a1 = *(const float4*)&Xs[k * BMP + ty * 8 + 4];
        float a[8] = {a0.x, a0.y, a0.z, a0.w, a1.x, a1.y, a1.z, a1.w};
        float b[8];
#pragma unroll
        for (int u = 0; u < 8; u++) b[u] = Ws[k * BMP + tx + 16 * u];
#pragma unroll
        for (int r = 0; r < 8; r++)
#pragma unroll
            for (int u = 0; u < 8; u++) acc[r][u] += a[r] * b[u];
    }

#pragma unroll
    for (int r = 0; r < 8; r++) {
        size_t ro = ((size_t)h * 16384 + rowbase + ty * 8 + r) * 128;
#pragma unroll
        for (int u = 0; u < 8; u++) H1[ro + tx + 16 * u] = acc[r][u];
    }
}

// ---------------------------------------------------------------------------
// feat2: H2 = X2 @ W_out. M=16384, K=1024, Ncols=64.
// Block: 256 threads, tile 128 rows x 64 cols, k-chunks of 64, 8x4 microtile.
// ---------------------------------------------------------------------------
__global__ __launch_bounds__(256, 1)
void feat2_kernel(const float* __restrict__ X2, const float* __restrict__ W,
                  float* __restrict__ H2)
{
    const int BMP = 132, BNP = 68;
    extern __shared__ float sm[];
    float* Xs = sm;               // [64][132]
    float* Ws = sm + 64 * BMP;    // [64][68]

    int tid = threadIdx.x, tx = tid & 15, ty = tid >> 4;
    int rowbase = blockIdx.x * 128;

    float acc[8][4];
#pragma unroll
    for (int r = 0; r < 8; r++)
#pragma unroll
        for (int u = 0; u < 4; u++) acc[r][u] = 0.0f;

    for (int kc = 0; kc < 16; kc++) {
        __syncthreads();
        for (int idx = tid; idx < 128 * 16; idx += 256) {
            int row = idx >> 4, c4 = idx & 15;
            float4 v = *(const float4*)(X2 + (size_t)(rowbase + row) * 1024 + kc * 64 + c4 * 4);
            Xs[(c4 * 4 + 0) * BMP + row] = v.x;
            Xs[(c4 * 4 + 1) * BMP + row] = v.y;
            Xs[(c4 * 4 + 2) * BMP + row] = v.z;
            Xs[(c4 * 4 + 3) * BMP + row] = v.w;
        }
        for (int idx = tid; idx < 64 * 16; idx += 256) {
            int k = idx >> 4, c4 = idx & 15;
            *(float4*)&Ws[k * BNP + c4 * 4] = *(const float4*)(W + (size_t)(kc * 64 + k) * 64 + c4 * 4);
        }
        __syncthreads();

#pragma unroll 4
        for (int k = 0; k < 64; k++) {
            float4 a0 = *(const float4*)&Xs[k * BMP + ty * 8];
            float4 a1 = *(const float4*)&Xs[k * BMP + ty * 8 + 4];
            float a[8] = {a0.x, a0.y, a0.z, a0.w, a1.x, a1.y, a1.z, a1.w};
            float b[4];
#pragma unroll
            for (int u = 0; u < 4; u++) b[u] = Ws[k * BNP + tx + 16 * u];
#pragma unroll
            for (int r = 0; r < 8; r++)
#pragma unroll
                for (int u = 0; u < 4; u++) acc[r][u] += a[r] * b[u];
        }
    }

#pragma unroll
    for (int r = 0; r < 8; r++) {
        size_t ro = (size_t)(rowbase + ty * 8 + r) * 64;
#pragma unroll
        for (int u = 0; u < 4; u++) H2[ro + tx + 16 * u] = acc[r][u];
    }
}

// ---------------------------------------------------------------------------
// Fused masked attention (flash-style, fp32):
//   out[i][:] = leaky_relu( softmax_m( mask(Q K^T) ) @ V + bias )
// Q = K = V = Hf slice [N][D]. Mask: s = dot * graph; s==0 -> -1e16.
// Grid: (N/128, B, Hheads). Block 256.  BM=128 query rows, BN=64 key chunk.
// smem: Qs[D][132] k-major, KsT[D][68] k-major, Vs[64][D+4] natural, Ps[64][132].
// All GEMM inner-loop smem loads are bank-conflict-free.
// ---------------------------------------------------------------------------
template <int D>
__global__ __launch_bounds__(256, 1)
void attn_kernel(const float* __restrict__ Hf, const float* __restrict__ graph,
                 const float* __restrict__ bias, float* __restrict__ out,
                 int out_stride)
{
    constexpr int BM = 128, BN = 64, BMP = 132, BNP = 68, DP = D + 4;
    constexpr int UO = D / 16;   // output cols per thread
    constexpr int NN = 1024;

    extern __shared__ float sm[];
    float* Qs  = sm;                       // D*BMP
    float* KsT = Qs + D * BMP;             // D*BNP
    float* Vs  = KsT + D * BNP;            // BN*DP
    float* Ps  = Vs + BN * DP;             // BN*BMP

    int tid = threadIdx.x, tx = tid & 15, ty = tid >> 4;
    int z = blockIdx.z, bb = blockIdx.y;
    int qbase = blockIdx.x * BM;

    const float* Hp = Hf + (size_t)(z * gridDim.y + bb) * NN * D;
    const float* bi = bias + (size_t)z * D;
    float* outp = out + (size_t)bb * NN * out_stride + (size_t)z * D;

    // Q tile transposed into smem: Qs[k][i]
    for (int idx = tid; idx < BM * (D / 4); idx += 256) {
        int row = idx / (D / 4), c4 = idx % (D / 4);
        float4 v = *(const float4*)(Hp + (size_t)(qbase + row) * D + c4 * 4);
        Qs[(c4 * 4 + 0) * BMP + row] = v.x;
        Qs[(c4 * 4 + 1) * BMP + row] = v.y;
        Qs[(c4 * 4 + 2) * BMP + row] = v.z;
        Qs[(c4 * 4 + 3) * BMP + row] = v.w;
    }

    float O[8][UO];
#pragma unroll
    for (int r = 0; r < 8; r++)
#pragma unroll
        for (int u = 0; u < UO; u++) O[r][u] = 0.0f;
    float mrow[8], lrow[8];
#pragma unroll
    for (int r = 0; r < 8; r++) { mrow[r] = -3.0e38f; lrow[r] = 0.0f; }

    for (int ch = 0; ch < NN / BN; ch++) {
        int kb = ch * BN;
        __syncthreads();   // prev GEMM2 done with KsT/Vs/Ps (also publishes Qs on ch==0)
        // load K/V chunk: both layouts
        for (int idx = tid; idx < BN * (D / 4); idx += 256) {
            int m = idx / (D / 4), c4 = idx % (D / 4);
            float4 v = *(const float4*)(Hp + (size_t)(kb + m) * D + c4 * 4);
            *(float4*)&Vs[m * DP + c4 * 4] = v;
            KsT[(c4 * 4 + 0) * BNP + m] = v.x;
            KsT[(c4 * 4 + 1) * BNP + m] = v.y;
            KsT[(c4 * 4 + 2) * BNP + m] = v.z;
            KsT[(c4 * 4 + 3) * BNP + m] = v.w;
        }
        __syncthreads();

        // GEMM1: S[i][m] = sum_k Q[i][k] K[m][k], rows i=ty*8+r, cols m=tx+16u
        float S[8][4];
#pragma unroll
        for (int r = 0; r < 8; r++)
#pragma unroll
            for (int u = 0; u < 4; u++) S[r][u] = 0.0f;
#pragma unroll 4
        for (int k = 0; k < D; k++) {
            float4 a0 = *(const float4*)&Qs[k * BMP + ty * 8];
            float4 a1 = *(const float4*)&Qs[k * BMP + ty * 8 + 4];
            float a[8] = {a0.x, a0.y, a0.z, a0.w, a1.x, a1.y, a1.z, a1.w};
            float bv[4];
#pragma unroll
            for (int u = 0; u < 4; u++) bv[u] = KsT[k * BNP + tx + 16 * u];
#pragma unroll
            for (int r = 0; r < 8; r++)
#pragma unroll
                for (int u = 0; u < 4; u++) S[r][u] += a[r] * bv[u];
        }

        // mask: s = dot * graph ; s==0 -> -1e16  (exactly like reference)
#pragma unroll
        for (int r = 0; r < 8; r++) {
            size_t grow = (size_t)(qbase + ty * 8 + r) * NN + kb;
#pragma unroll
            for (int u = 0; u < 4; u++) {
                float g = graph[grow + tx + 16 * u];
                float s = S[r][u] * g;
                S[r][u] = (s == 0.0f) ? -1e16f : s;
            }
        }

        // online softmax update (row state replicated across the 16 tx lanes)
#pragma unroll
        for (int r = 0; r < 8; r++) {
            float mx = S[r][0];
#pragma unroll
            for (int u = 1; u < 4; u++) mx = fmaxf(mx, S[r][u]);
            mx = fmaxf(mx, __shfl_xor_sync(0xffffffffu, mx, 1));
            mx = fmaxf(mx, __shfl_xor_sync(0xffffffffu, mx, 2));
            mx = fmaxf(mx, __shfl_xor_sync(0xffffffffu, mx, 4));
            mx = fmaxf(mx, __shfl_xor_sync(0xffffffffu, mx, 8));
            float mn = fmaxf(mrow[r], mx);
            float alpha = exp2f((mrow[r] - mn) * LOG2E);
            mrow[r] = mn;
            float rs = 0.0f;
#pragma unroll
            for (int u = 0; u < 4; u++) {
                float p = exp2f((S[r][u] - mn) * LOG2E);
                S[r][u] = p;
                rs += p;
            }
            rs += __shfl_xor_sync(0xffffffffu, rs, 1);
            rs += __shfl_xor_sync(0xffffffffu, rs, 2);
            rs += __shfl_xor_sync(0xffffffffu, rs, 4);
            rs += __shfl_xor_sync(0xffffffffu, rs, 8);
            lrow[r] = lrow[r] * alpha + rs;
#pragma unroll
            for (int u = 0; u < UO; u++) O[r][u] *= alpha;
        }

        // write P to smem: Ps[m][i]
#pragma unroll
        for (int u = 0; u < 4; u++) {
            int m = tx + 16 * u;
            float4 p0 = make_float4(S[0][u], S[1][u], S[2][u], S[3][u]);
            float4 p1 = make_float4(S[4][u], S[5][u], S[6][u], S[7][u]);
            *(float4*)&Ps[m * BMP + ty * 8]     = p0;
            *(float4*)&Ps[m * BMP + ty * 8 + 4] = p1;
        }
        __syncthreads();

        // GEMM2: O[i][j] += sum_m P[i][m] V[m][j]
#pragma unroll 2
        for (int m = 0; m < BN; m++) {
            float4 p0 = *(const float4*)&Ps[m * BMP + ty * 8];
            float4 p1 = *(const float4*)&Ps[m * BMP + ty * 8 + 4];
            float p[8] = {p0.x, p0.y, p0.z, p0.w, p1.x, p1.y, p1.z, p1.w};
            float vv[UO];
#pragma unroll
            for (int u = 0; u < UO; u++) vv[u] = Vs[m * DP + tx + 16 * u];
#pragma unroll
            for (int r = 0; r < 8; r++)
#pragma unroll
                for (int u = 0; u < UO; u++) O[r][u] += p[r] * vv[u];
        }
    }

    // epilogue: normalize, + bias, leaky relu, store
#pragma unroll
    for (int r = 0; r < 8; r++) {
        float inv = 1.0f / lrow[r];
        size_t ro = (size_t)(qbase + ty * 8 + r) * out_stride;
#pragma unroll
        for (int u = 0; u < UO; u++) {
            float v = O[r][u] * inv + bi[tx + 16 * u];
            v = (v > 0.0f) ? v : 0.01f * v;
            outp[ro + tx + 16 * u] = v;
        }
    }
}

// ---------------------------------------------------------------------------
// host launcher
// ---------------------------------------------------------------------------
extern "C" void kernel_launch(void* const* d_in, const int* in_sizes, int n_in,
                              void* d_out, int out_size)
{
    const float* x     = (const float*)d_in[0];   // [16,1024,64]
    const float* graph = (const float*)d_in[1];   // [1024,1024]
    const float* Wh    = (const float*)d_in[2];   // [8,64,128]
    const float* bh    = (const float*)d_in[3];   // [8,128]
    const float* W_out = (const float*)d_in[4];   // [1024,64]
    const float* b_out = (const float*)d_in[5];   // [64]
    float* out = (float*)d_out;                   // [16,1024,64]

    float *H1, *X2, *H2;
    cudaGetSymbolAddress((void**)&H1, g_H1);
    cudaGetSymbolAddress((void**)&X2, g_X2);
    cudaGetSymbolAddress((void**)&H2, g_H2);

    const int FEAT1_SMEM = (64 * 132) * 2 * 4;                                    // 67.6 KB
    const int FEAT2_SMEM = (64 * 132 + 64 * 68) * 4;                              // 51.2 KB
    const int ATTN1_SMEM = (128 * 132 + 128 * 68 + 64 * 132 + 64 * 132) * 4;      // 170 KB
    const int ATTN2_SMEM = (64 * 132 + 64 * 68 + 64 * 68 + 64 * 132) * 4;         // 102 KB

    cudaFuncSetAttribute(feat1_kernel, cudaFuncAttributeMaxDynamicSharedMemorySize, FEAT1_SMEM);
    cudaFuncSetAttribute(feat2_kernel, cudaFuncAttributeMaxDynamicSharedMemorySize, FEAT2_SMEM);
    cudaFuncSetAttribute(attn_kernel<128>, cudaFuncAttributeMaxDynamicSharedMemorySize, ATTN1_SMEM);
    cudaFuncSetAttribute(attn_kernel<64>, cudaFuncAttributeMaxDynamicSharedMemorySize, ATTN2_SMEM);

    // layer 1: features then fused masked attention (writes concat + leaky relu)
    feat1_kernel<<<dim3(128, 8), 256, FEAT1_SMEM>>>(x, Wh, H1);
    attn_kernel<128><<<dim3(8, 16, 8), 256, ATTN1_SMEM>>>(H1, graph, bh, X2, 1024);

    // layer 2
    feat2_kernel<<<dim3(128), 256, FEAT2_SMEM>>>(X2, W_out, H2);
    attn_kernel<64><<<dim3(8, 16, 1), 256, ATTN2_SMEM>>>(H2, graph, b_out, out, 64);
}

// round 11
// speedup vs baseline: 1.1683x; 1.1683x over previous
#include <cuda_runtime.h>
#include <cstdint>

// GATNet on GB300: both attention layers on tensor cores via 3xTF32 mma.sync.
// B=16, N=1024, CIN=64, D=128, H=8, COUT=64

#define LOG2E 1.4426950408889634f
static const int NV = 1024, BV = 16, DHD = 128, NHV = 8, COUT = 64;

__device__ float g_H1[(size_t)NHV * BV * NV * DHD];   // 67 MB
__device__ float g_X2[(size_t)BV * NV * (NHV * DHD)]; // 64 MB
__device__ float g_H2[(size_t)BV * NV * COUT];        // 4 MB

__device__ __forceinline__ float to_tf32(float x) {
    unsigned u;
    asm("cvt.rna.tf32.f32 %0, %1;" : "=r"(u) : "f"(x));
    return __uint_as_float(u);
}
__device__ __forceinline__ void mma8(float* d, const float* a, const float* b) {
    asm volatile(
        "mma.sync.aligned.m16n8k8.row.col.f32.tf32.tf32.f32 "
        "{%0,%1,%2,%3}, {%4,%5,%6,%7}, {%8,%9}, {%0,%1,%2,%3};"
        : "+f"(d[0]), "+f"(d[1]), "+f"(d[2]), "+f"(d[3])
        : "r"(__float_as_uint(a[0])), "r"(__float_as_uint(a[1])),
          "r"(__float_as_uint(a[2])), "r"(__float_as_uint(a[3])),
          "r"(__float_as_uint(b[0])), "r"(__float_as_uint(b[1])));
}

// ---------------------------------------------------------------------------
// Unified fp32 feature GEMM: out[y][row][0:NC] = x[row][0:KTOT] @ W[y]
// grid.y selects head (feat1) or is 1 (feat2). 256 thr, 128-row tiles.
// ---------------------------------------------------------------------------
template <int KTOT, int NC>
__global__ __launch_bounds__(256, 1)
void feat_kernel(const float* __restrict__ x, const float* __restrict__ Wall,
                 float* __restrict__ outp)
{
    const int BMP = 132, NCP = NC + 4;
    constexpr int U = NC / 16;
    extern __shared__ float sm[];
    float* Xs = sm;               // [64][132] k-major
    float* Ws = sm + 64 * BMP;    // [64][NCP]

    int tid = threadIdx.x, tx = tid & 15, ty = tid >> 4;
    int rowbase = blockIdx.x * 128;
    const float* W = Wall + (size_t)blockIdx.y * KTOT * NC;

    float acc[8][U];
#pragma unroll
    for (int r = 0; r < 8; r++)
#pragma unroll
        for (int u = 0; u < U; u++) acc[r][u] = 0.0f;

    for (int kc = 0; kc < KTOT / 64; kc++) {
        __syncthreads();
        for (int idx = tid; idx < 128 * 16; idx += 256) {
            int row = idx >> 4, c4 = idx & 15;
            float4 v = *(const float4*)(x + (size_t)(rowbase + row) * KTOT + kc * 64 + c4 * 4);
            Xs[(c4 * 4 + 0) * BMP + row] = v.x;
            Xs[(c4 * 4 + 1) * BMP + row] = v.y;
            Xs[(c4 * 4 + 2) * BMP + row] = v.z;
            Xs[(c4 * 4 + 3) * BMP + row] = v.w;
        }
        for (int idx = tid; idx < 64 * (NC / 4); idx += 256) {
            int k = idx / (NC / 4), c4 = idx % (NC / 4);
            *(float4*)&Ws[k * NCP + c4 * 4] =
                *(const float4*)(W + (size_t)(kc * 64 + k) * NC + c4 * 4);
        }
        __syncthreads();
#pragma unroll 4
        for (int k = 0; k < 64; k++) {
            float4 a0 = *(const float4*)&Xs[k * BMP + ty * 8];
            float4 a1 = *(const float4*)&Xs[k * BMP + ty * 8 + 4];
            float a[8] = {a0.x, a0.y, a0.z, a0.w, a1.x, a1.y, a1.z, a1.w};
            float b[U];
#pragma unroll
            for (int u = 0; u < U; u++) b[u] = Ws[k * NCP + tx + 16 * u];
#pragma unroll
            for (int r = 0; r < 8; r++)
#pragma unroll
                for (int u = 0; u < U; u++) acc[r][u] += a[r] * b[u];
        }
    }
#pragma unroll
    for (int r = 0; r < 8; r++) {
        size_t ro = ((size_t)blockIdx.y * 16384 + rowbase + ty * 8 + r) * NC;
#pragma unroll
        for (int u = 0; u < U; u++) outp[ro + tx + 16 * u] = acc[r][u];
    }
}

// ---------------------------------------------------------------------------
// Tensor-core masked flash attention (3xTF32):
//   out = leaky_relu( softmax(mask(H H^T)) @ H + bias )
// grid (N/64, B, heads). 256 thr = 8 warps: wm=wid>>1 (16-row group),
// wn=wid&1 (N-half for scores, D-half for PV). K/V share one smem copy.
// ---------------------------------------------------------------------------
template <int D>
__global__ __launch_bounds__(256, 1)
void attn_tc(const float* __restrict__ Hf, const float* __restrict__ graph,
             const float* __restrict__ bias, float* __restrict__ out,
             int out_stride)
{
    constexpr int BM = 64, BN = 64, DP = D + 4, NN = 1024, DH2 = D / 2;
    constexpr int NF = DH2 / 8;   // O col-frags per warp
    extern __shared__ float sm[];
    float* QH = sm;                 // [BM][DP] tf32-hi of Q
    float* QL = QH + BM * DP;       // tf32-lo
    float* KH = QL + BM * DP;       // [BN][DP] chunk hi (K and V)
    float* KL = KH + BN * DP;
    float* PH = KL + BN * DP;       // [BM][68] raw scores -> P hi
    float* PL = PH + BM * 68;       // P lo
    float* MR = PL + BM * 68;       // [BM] running max
    float* LR = MR + BM;            // [BM] running sum
    float* AL = LR + BM;            // [BM] alpha

    int tid = threadIdx.x, lane = tid & 31, wid = tid >> 5;
    int wm = wid >> 1, wn = wid & 1;
    int z = blockIdx.z, bb = blockIdx.y, qbase = blockIdx.x * BM;
    const float* Hp = Hf + (size_t)(z * gridDim.y + bb) * NN * D;

    // load + split Q tile
    for (int idx = tid; idx < BM * (D / 4); idx += 256) {
        int r = idx / (D / 4), c4 = idx % (D / 4);
        float4 v = *(const float4*)(Hp + (size_t)(qbase + r) * D + c4 * 4);
        float* qh = &QH[r * DP + c4 * 4];
        float* ql = &QL[r * DP + c4 * 4];
        float h;
        h = to_tf32(v.x); qh[0] = h; ql[0] = to_tf32(v.x - h);
        h = to_tf32(v.y); qh[1] = h; ql[1] = to_tf32(v.y - h);
        h = to_tf32(v.z); qh[2] = h; ql[2] = to_tf32(v.z - h);
        h = to_tf32(v.w); qh[3] = h; ql[3] = to_tf32(v.w - h);
    }
    if (tid < BM) { MR[tid] = -3.0e38f; LR[tid] = 0.0f; }

    float O[NF][4];
#pragma unroll
    for (int f = 0; f < NF; f++)
#pragma unroll
        for (int i = 0; i < 4; i++) O[f][i] = 0.0f;

    const int r0 = wm * 16 + (lane >> 2);

    for (int ch = 0; ch < NN / BN; ch++) {
        int kb = ch * BN;
        __syncthreads();
        // load + split K/V chunk
        for (int idx = tid; idx < BN * (D / 4); idx += 256) {
            int r = idx / (D / 4), c4 = idx % (D / 4);
            float4 v = *(const float4*)(Hp + (size_t)(kb + r) * D + c4 * 4);
            float* kh = &KH[r * DP + c4 * 4];
            float* kl = &KL[r * DP + c4 * 4];
            float h;
            h = to_tf32(v.x); kh[0] = h; kl[0] = to_tf32(v.x - h);
            h = to_tf32(v.y); kh[1] = h; kl[1] = to_tf32(v.y - h);
            h = to_tf32(v.z); kh[2] = h; kl[2] = to_tf32(v.z - h);
            h = to_tf32(v.w); kh[3] = h; kl[3] = to_tf32(v.w - h);
        }
        __syncthreads();

        // scores: warp rows [wm*16,+16), cols [wn*32,+32)
        float S[4][4];
#pragma unroll
        for (int f = 0; f < 4; f++)
#pragma unroll
            for (int i = 0; i < 4; i++) S[f][i] = 0.0f;
#pragma unroll
        for (int k = 0; k < D; k += 8) {
            int ac = k + (lane & 3);
            float ah[4] = {QH[r0 * DP + ac], QH[(r0 + 8) * DP + ac],
                           QH[r0 * DP + ac + 4], QH[(r0 + 8) * DP + ac + 4]};
            float al[4] = {QL[r0 * DP + ac], QL[(r0 + 8) * DP + ac],
                           QL[r0 * DP + ac + 4], QL[(r0 + 8) * DP + ac + 4]};
#pragma unroll
            for (int f = 0; f < 4; f++) {
                int br = wn * 32 + f * 8 + (lane >> 2);
                float bh[2] = {KH[br * DP + ac], KH[br * DP + ac + 4]};
                float bl[2] = {KL[br * DP + ac], KL[br * DP + ac + 4]};
                mma8(S[f], ah, bh);
                mma8(S[f], ah, bl);
                mma8(S[f], al, bh);
            }
        }

        // mask (s*g; s==0 -> -1e16) and stage raw scores
#pragma unroll
        for (int f = 0; f < 4; f++) {
            int n0 = wn * 32 + f * 8 + 2 * (lane & 3);
#pragma unroll
            for (int hh = 0; hh < 2; hh++) {
                int rr = r0 + hh * 8;
                const float* gr = graph + (size_t)(qbase + rr) * NN + kb;
                float s0 = S[f][hh * 2 + 0] * gr[n0];
                float s1 = S[f][hh * 2 + 1] * gr[n0 + 1];
                PH[rr * 68 + n0]     = (s0 == 0.0f) ? -1e16f : s0;
                PH[rr * 68 + n0 + 1] = (s1 == 0.0f) ? -1e16f : s1;
            }
        }
        __syncthreads();

        // online softmax: 8 warps x 8 rows, 4 lanes/row x 16 cols
        {
            int row = wid * 8 + (lane >> 2);
            float* pr = PH + row * 68 + (lane & 3) * 16;
            float* plr = PL + row * 68 + (lane & 3) * 16;
            float mx = -3.0e38f;
#pragma unroll
            for (int c = 0; c < 16; c++) mx = fmaxf(mx, pr[c]);
            mx = fmaxf(mx, __shfl_xor_sync(0xffffffffu, mx, 1));
            mx = fmaxf(mx, __shfl_xor_sync(0xffffffffu, mx, 2));
            float mold = MR[row];
            float mnew = fmaxf(mold, mx);
            float rs = 0.0f;
#pragma unroll
            for (int c = 0; c < 16; c++) {
                float p = exp2f((pr[c] - mnew) * LOG2E);
                rs += p;
                float ph = to_tf32(p);
                pr[c] = ph;
                plr[c] = to_tf32(p - ph);
            }
            rs += __shfl_xor_sync(0xffffffffu, rs, 1);
            rs += __shfl_xor_sync(0xffffffffu, rs, 2);
            if ((lane & 3) == 0) {
                float a = exp2f((mold - mnew) * LOG2E);
                MR[row] = mnew;
                LR[row] = LR[row] * a + rs;
                AL[row] = a;
            }
        }
        __syncthreads();

        // rescale O, then O += P @ V (V = same chunk rows, hi/lo in KH/KL)
        {
            float a0 = AL[r0], a1 = AL[r0 + 8];
#pragma unroll
            for (int f = 0; f < NF; f++) {
                O[f][0] *= a0; O[f][1] *= a0; O[f][2] *= a1; O[f][3] *= a1;
            }
#pragma unroll
            for (int k = 0; k < BN; k += 8) {
                int pc = k + (lane & 3);
                float ah[4] = {PH[r0 * 68 + pc], PH[(r0 + 8) * 68 + pc],
                               PH[r0 * 68 + pc + 4], PH[(r0 + 8) * 68 + pc + 4]};
                float al[4] = {PL[r0 * 68 + pc], PL[(r0 + 8) * 68 + pc],
                               PL[r0 * 68 + pc + 4], PL[(r0 + 8) * 68 + pc + 4]};
#pragma unroll
                for (int f = 0; f < NF; f++) {
                    int dc = wn * DH2 + f * 8 + (lane >> 2);
                    int vr = k + (lane & 3);
                    float bh[2] = {KH[vr * DP + dc], KH[(vr + 4) * DP + dc]};
                    float bl[2] = {KL[vr * DP + dc], KL[(vr + 4) * DP + dc]};
                    mma8(O[f], ah, bh);
                    mma8(O[f], ah, bl);
                    mma8(O[f], al, bh);
                }
            }
        }
    }

    // epilogue: /l, +bias, leaky relu, store
    float inv0 = 1.0f / LR[r0], inv1 = 1.0f / LR[r0 + 8];
    const float* bi = bias + (size_t)z * D;
    float* op = out + (size_t)bb * NN * out_stride + (size_t)z * D;
#pragma unroll
    for (int f = 0; f < NF; f++) {
        int d0 = wn * DH2 + f * 8 + 2 * (lane & 3);
        float b0 = bi[d0], b1 = bi[d0 + 1];
        float v;
        v = O[f][0] * inv0 + b0; v = v > 0.0f ? v : 0.01f * v;
        op[(size_t)(qbase + r0) * out_stride + d0] = v;
        v = O[f][1] * inv0 + b1; v = v > 0.0f ? v : 0.01f * v;
        op[(size_t)(qbase + r0) * out_stride + d0 + 1] = v;
        v = O[f][2] * inv1 + b0; v = v > 0.0f ? v : 0.01f * v;
        op[(size_t)(qbase + r0 + 8) * out_stride + d0] = v;
        v = O[f][3] * inv1 + b1; v = v > 0.0f ? v : 0.01f * v;
        op[(size_t)(qbase + r0 + 8) * out_stride + d0 + 1] = v;
    }
}

// ---------------------------------------------------------------------------
extern "C" void kernel_launch(void* const* d_in, const int* in_sizes, int n_in,
                              void* d_out, int out_size)
{
    const float* x     = (const float*)d_in[0];
    const float* graph = (const float*)d_in[1];
    const float* Wh    = (const float*)d_in[2];
    const float* bh    = (const float*)d_in[3];
    const float* W_out = (const float*)d_in[4];
    const float* b_out = (const float*)d_in[5];
    float* out = (float*)d_out;

    float *H1, *X2, *H2;
    cudaGetSymbolAddress((void**)&H1, g_H1);
    cudaGetSymbolAddress((void**)&X2, g_X2);
    cudaGetSymbolAddress((void**)&H2, g_H2);

    const int F1_SMEM = (64 * 132 + 64 * 132) * 4;
    const int F2_SMEM = (64 * 132 + 64 * 68) * 4;
    const int A1_SMEM = (4 * 64 * 132 + 2 * 64 * 68 + 3 * 64) * 4;  // 170752
    const int A2_SMEM = (4 * 64 * 68 + 2 * 64 * 68 + 3 * 64) * 4;   // 105216

    cudaFuncSetAttribute(feat_kernel<64, 128>, cudaFuncAttributeMaxDynamicSharedMemorySize, F1_SMEM);
    cudaFuncSetAttribute(feat_kernel<1024, 64>, cudaFuncAttributeMaxDynamicSharedMemorySize, F2_SMEM);
    cudaFuncSetAttribute(attn_tc<128>, cudaFuncAttributeMaxDynamicSharedMemorySize, A1_SMEM);
    cudaFuncSetAttribute(attn_tc<64>, cudaFuncAttributeMaxDynamicSharedMemorySize, A2_SMEM);

    feat_kernel<64, 128><<<dim3(128, 8), 256, F1_SMEM>>>(x, Wh, H1);
    attn_tc<128><<<dim3(16, 16, 8), 256, A1_SMEM>>>(H1, graph, bh, X2, 1024);
    feat_kernel<1024, 64><<<dim3(128, 1), 256, F2_SMEM>>>(X2, W_out, H2);
    attn_tc<64><<<dim3(16, 16, 1), 256, A2_SMEM>>>(H2, graph, b_out, out, 64);
}

// round 15
// speedup vs baseline: 1.1830x; 1.0126x over previous
#include <cuda_runtime.h>
#include <cstdint>

// GATNet on GB300: attention on tensor cores via 3xTF32 mma.sync, v2.
// v2: fp32 operands in smem + register-side tf32 hi/lo split (halves LDS bytes),
//     BM=128 with 32x32 score warp tiles (more reuse + ILP), transposed V copy.
// B=16, N=1024, CIN=64, D=128, H=8, COUT=64

#define LOG2E 1.4426950408889634f
static const int NV = 1024, BV = 16, DHD = 128, NHV = 8, COUT = 64;

__device__ float g_H1[(size_t)NHV * BV * NV * DHD];   // 67 MB
__device__ float g_X2[(size_t)BV * NV * (NHV * DHD)]; // 64 MB
__device__ float g_H2[(size_t)BV * NV * COUT];        // 4 MB

__device__ __forceinline__ float to_tf32(float x) {
    unsigned u;
    asm("cvt.rna.tf32.f32 %0, %1;" : "=r"(u) : "f"(x));
    return __uint_as_float(u);
}
__device__ __forceinline__ void split2(float v, float& h, float& l) {
    h = to_tf32(v);
    l = to_tf32(v - h);
}
__device__ __forceinline__ void mma8(float* d, const float* a, const float* b) {
    asm volatile(
        "mma.sync.aligned.m16n8k8.row.col.f32.tf32.tf32.f32 "
        "{%0,%1,%2,%3}, {%4,%5,%6,%7}, {%8,%9}, {%0,%1,%2,%3};"
        : "+f"(d[0]), "+f"(d[1]), "+f"(d[2]), "+f"(d[3])
        : "r"(__float_as_uint(a[0])), "r"(__float_as_uint(a[1])),
          "r"(__float_as_uint(a[2])), "r"(__float_as_uint(a[3])),
          "r"(__float_as_uint(b[0])), "r"(__float_as_uint(b[1])));
}

// ---------------------------------------------------------------------------
// Unified fp32 feature GEMM (unchanged from passing R11 kernel).
// ---------------------------------------------------------------------------
template <int KTOT, int NC>
__global__ __launch_bounds__(256, 1)
void feat_kernel(const float* __restrict__ x, const float* __restrict__ Wall,
                 float* __restrict__ outp)
{
    const int BMP = 132, NCP = NC + 4;
    constexpr int U = NC / 16;
    extern __shared__ float sm[];
    float* Xs = sm;
    float* Ws = sm + 64 * BMP;

    int tid = threadIdx.x, tx = tid & 15, ty = tid >> 4;
    int rowbase = blockIdx.x * 128;
    const float* W = Wall + (size_t)blockIdx.y * KTOT * NC;

    float acc[8][U];
#pragma unroll
    for (int r = 0; r < 8; r++)
#pragma unroll
        for (int u = 0; u < U; u++) acc[r][u] = 0.0f;

    for (int kc = 0; kc < KTOT / 64; kc++) {
        __syncthreads();
        for (int idx = tid; idx < 128 * 16; idx += 256) {
            int row = idx >> 4, c4 = idx & 15;
            float4 v = *(const float4*)(x + (size_t)(rowbase + row) * KTOT + kc * 64 + c4 * 4);
            Xs[(c4 * 4 + 0) * BMP + row] = v.x;
            Xs[(c4 * 4 + 1) * BMP + row] = v.y;
            Xs[(c4 * 4 + 2) * BMP + row] = v.z;
            Xs[(c4 * 4 + 3) * BMP + row] = v.w;
        }
        for (int idx = tid; idx < 64 * (NC / 4); idx += 256) {
            int k = idx / (NC / 4), c4 = idx % (NC / 4);
            *(float4*)&Ws[k * NCP + c4 * 4] =
                *(const float4*)(W + (size_t)(kc * 64 + k) * NC + c4 * 4);
        }
        __syncthreads();
#pragma unroll 4
        for (int k = 0; k < 64; k++) {
            float4 a0 = *(const float4*)&Xs[k * BMP + ty * 8];
            float4 a1 = *(const float4*)&Xs[k * BMP + ty * 8 + 4];
            float a[8] = {a0.x, a0.y, a0.z, a0.w, a1.x, a1.y, a1.z, a1.w};
            float b[U];
#pragma unroll
            for (int u = 0; u < U; u++) b[u] = Ws[k * NCP + tx + 16 * u];
#pragma unroll
            for (int r = 0; r < 8; r++)
#pragma unroll
                for (int u = 0; u < U; u++) acc[r][u] += a[r] * b[u];
        }
    }
#pragma unroll
    for (int r = 0; r < 8; r++) {
        size_t ro = ((size_t)blockIdx.y * 16384 + rowbase + ty * 8 + r) * NC;
#pragma unroll
        for (int u = 0; u < U; u++) outp[ro + tx + 16 * u] = acc[r][u];
    }
}

// ---------------------------------------------------------------------------
// Tensor-core masked flash attention v2 (3xTF32, register-side split).
// grid (N/128, B, heads). 256 thr = 8 warps = 4 M-groups (32 rows) x 2 N-groups.
// smem: QF[128][D+4] fp32, KF[64][D+4] fp32, VT[D][68] fp32 (transposed V),
//       PF[128][68] raw scores -> p (fp32), MR/LR/AL[128].
// ---------------------------------------------------------------------------
template <int D>
__global__ __launch_bounds__(256, 1)
void attn_tc(const float* __restrict__ Hf, const float* __restrict__ graph,
             const float* __restrict__ bias, float* __restrict__ out,
             int out_stride)
{
    constexpr int BM = 128, BN = 64, DP = D + 4, NN = 1024;
    constexpr int NO = D / 16;   // n8 O-frags per warp (covers D/2 cols)
    extern __shared__ float sm[];
    float* QF = sm;                  // BM*DP
    float* KF = QF + BM * DP;        // BN*DP
    float* VT = KF + BN * DP;        // D*68
    float* PF = VT + D * 68;         // BM*68
    float* MR = PF + BM * 68;        // BM
    float* LR = MR + BM;             // BM
    float* AL = LR + BM;             // BM

    int tid = threadIdx.x, lane = tid & 31, wid = tid >> 5;
    int wm = wid >> 1, wn = wid & 1;
    int g = lane >> 2, t4 = lane & 3;
    int z = blockIdx.z, bb = blockIdx.y, qbase = blockIdx.x * BM;
    const float* Hp = Hf + (size_t)(z * gridDim.y + bb) * NN * D;

    const int R  = wm * 32;        // warp row base (scores & PV)
    const int C  = wn * 32;        // warp score-col base
    const int CD = wn * (D / 2);   // warp PV D-col base

    // load Q tile (plain fp32)
    for (int idx = tid; idx < BM * (D / 4); idx += 256) {
        int r = idx / (D / 4), c4 = idx % (D / 4);
        *(float4*)&QF[r * DP + c4 * 4] =
            *(const float4*)(Hp + (size_t)(qbase + r) * D + c4 * 4);
    }
    if (tid < BM) { MR[tid] = -3.0e38f; LR[tid] = 0.0f; }

    float O[2][NO][4];
#pragma unroll
    for (int m = 0; m < 2; m++)
#pragma unroll
        for (int n = 0; n < NO; n++)
#pragma unroll
            for (int i = 0; i < 4; i++) O[m][n][i] = 0.0f;

    for (int ch = 0; ch < NN / BN; ch++) {
        int kb = ch * BN;
        __syncthreads();
        // load K/V chunk: KF natural + VT transposed
        for (int idx = tid; idx < BN * (D / 4); idx += 256) {
            int r = idx / (D / 4), c4 = idx % (D / 4);
            float4 v = *(const float4*)(Hp + (size_t)(kb + r) * D + c4 * 4);
            *(float4*)&KF[r * DP + c4 * 4] = v;
            VT[(c4 * 4 + 0) * 68 + r] = v.x;
            VT[(c4 * 4 + 1) * 68 + r] = v.y;
            VT[(c4 * 4 + 2) * 68 + r] = v.z;
            VT[(c4 * 4 + 3) * 68 + r] = v.w;
        }
        __syncthreads();

        // ---- scores: warp tile 32x32 = 2 m16 x 4 n8, 3-term split ----
        float S[2][4][4];
#pragma unroll
        for (int m = 0; m < 2; m++)
#pragma unroll
            for (int f = 0; f < 4; f++)
#pragma unroll
                for (int i = 0; i < 4; i++) S[m][f][i] = 0.0f;

#pragma unroll
        for (int k = 0; k < D; k += 8) {
            float ah[2][4], al_[2][4];
#pragma unroll
            for (int m = 0; m < 2; m++) {
                int rm = R + m * 16 + g;
                split2(QF[rm * DP + k + t4],           ah[m][0], al_[m][0]);
                split2(QF[(rm + 8) * DP + k + t4],     ah[m][1], al_[m][1]);
                split2(QF[rm * DP + k + 4 + t4],       ah[m][2], al_[m][2]);
                split2(QF[(rm + 8) * DP + k + 4 + t4], ah[m][3], al_[m][3]);
            }
#pragma unroll
            for (int f = 0; f < 4; f++) {
                int nb = C + f * 8 + g;
                float bh[2], bl[2];
                split2(KF[nb * DP + k + t4],     bh[0], bl[0]);
                split2(KF[nb * DP + k + 4 + t4], bh[1], bl[1]);
#pragma unroll
                for (int m = 0; m < 2; m++) {
                    mma8(S[m][f], ah[m], bh);
                    mma8(S[m][f], ah[m], bl);
                    mma8(S[m][f], al_[m], bh);
                }
            }
        }

        // mask (s*graph; s==0 -> -1e16), stage raw scores to PF
#pragma unroll
        for (int m = 0; m < 2; m++) {
            int ra = R + m * 16 + g, rb = ra + 8;
            const float* gra = graph + (size_t)(qbase + ra) * NN + kb;
            const float* grb = graph + (size_t)(qbase + rb) * NN + kb;
#pragma unroll
            for (int f = 0; f < 4; f++) {
                int n0 = C + f * 8 + 2 * t4;
                float s;
                s = S[m][f][0] * gra[n0];     PF[ra * 68 + n0]     = (s == 0.0f) ? -1e16f : s;
                s = S[m][f][1] * gra[n0 + 1]; PF[ra * 68 + n0 + 1] = (s == 0.0f) ? -1e16f : s;
                s = S[m][f][2] * grb[n0];     PF[rb * 68 + n0]     = (s == 0.0f) ? -1e16f : s;
                s = S[m][f][3] * grb[n0 + 1]; PF[rb * 68 + n0 + 1] = (s == 0.0f) ? -1e16f : s;
            }
        }
        __syncthreads();

        // ---- online softmax: row = wid*16 + (lane&15); cols (lane>>4) + 2c ----
        {
            int row = wid * 16 + (lane & 15);
            int c0 = lane >> 4;
            float* pr = PF + row * 68 + c0;
            float mx = -3.0e38f;
#pragma unroll
            for (int c = 0; c < 32; c++) mx = fmaxf(mx, pr[2 * c]);
            mx = fmaxf(mx, __shfl_xor_sync(0xffffffffu, mx, 16));
            float mold = MR[row];
            float mnew = fmaxf(mold, mx);
            float rs = 0.0f;
#pragma unroll
            for (int c = 0; c < 32; c++) {
                float p = exp2f((pr[2 * c] - mnew) * LOG2E);
                rs += p;
                pr[2 * c] = p;
            }
            rs += __shfl_xor_sync(0xffffffffu, rs, 16);
            if (c0 == 0) {
                float a = exp2f((mold - mnew) * LOG2E);
                MR[row] = mnew;
                LR[row] = LR[row] * a + rs;
                AL[row] = a;
            }
        }
        __syncthreads();

        // ---- rescale O, then O += P @ V (warp tile 32 x D/2) ----
#pragma unroll
        for (int m = 0; m < 2; m++) {
            float a0 = AL[R + m * 16 + g], a1 = AL[R + m * 16 + 8 + g];
#pragma unroll
            for (int n = 0; n < NO; n++) {
                O[m][n][0] *= a0; O[m][n][1] *= a0;
                O[m][n][2] *= a1; O[m][n][3] *= a1;
            }
        }
#pragma unroll
        for (int kk = 0; kk < BN; kk += 8) {
            float ph_[2][4], pl_[2][4];
#pragma unroll
            for (int m = 0; m < 2; m++) {
                int rm = R + m * 16 + g;
                split2(PF[rm * 68 + kk + t4],           ph_[m][0], pl_[m][0]);
                split2(PF[(rm + 8) * 68 + kk + t4],     ph_[m][1], pl_[m][1]);
                split2(PF[rm * 68 + kk + 4 + t4],       ph_[m][2], pl_[m][2]);
                split2(PF[(rm + 8) * 68 + kk + 4 + t4], ph_[m][3], pl_[m][3]);
            }
#pragma unroll
            for (int n = 0; n < NO; n++) {
                int dc = CD + n * 8 + g;
                float vh[2], vl[2];
                split2(VT[dc * 68 + kk + t4],     vh[0], vl[0]);
                split2(VT[dc * 68 + kk + 4 + t4], vh[1], vl[1]);
#pragma unroll
                for (int m = 0; m < 2; m++) {
                    mma8(O[m][n], ph_[m], vh);
                    mma8(O[m][n], ph_[m], vl);
                    mma8(O[m][n], pl_[m], vh);
                }
            }
        }
    }

    // ---- epilogue: /l, +bias, leaky relu, store ----
    const float* bi = bias + (size_t)z * D;
    float* op = out + (size_t)bb * NN * out_stride + (size_t)z * D;
#pragma unroll
    for (int m = 0; m < 2; m++) {
        int ra = R + m * 16 + g, rb = ra + 8;
        float inva = 1.0f / LR[ra], invb = 1.0f / LR[rb];
#pragma unroll
        for (int n = 0; n < NO; n++) {
            int d0 = CD + n * 8 + 2 * t4;
            float b0 = bi[d0], b1 = bi[d0 + 1];
            float v;
            v = O[m][n][0] * inva + b0; v = v > 0.0f ? v : 0.01f * v;
            op[(size_t)(qbase + ra) * out_stride + d0] = v;
            v = O[m][n][1] * inva + b1; v = v > 0.0f ? v : 0.01f * v;
            op[(size_t)(qbase + ra) * out_stride + d0 + 1] = v;
            v = O[m][n][2] * invb + b0; v = v > 0.0f ? v : 0.01f * v;
            op[(size_t)(qbase + rb) * out_stride + d0] = v;
            v = O[m][n][3] * invb + b1; v = v > 0.0f ? v : 0.01f * v;
            op[(size_t)(qbase + rb) * out_stride + d0 + 1] = v;
        }
    }
}

// ---------------------------------------------------------------------------
extern "C" void kernel_launch(void* const* d_in, const int* in_sizes, int n_in,
                              void* d_out, int out_size)
{
    const float* x     = (const float*)d_in[0];
    const float* graph = (const float*)d_in[1];
    const float* Wh    = (const float*)d_in[2];
    const float* bh    = (const float*)d_in[3];
    const float* W_out = (const float*)d_in[4];
    const float* b_out = (const float*)d_in[5];
    float* out = (float*)d_out;

    float *H1, *X2, *H2;
    cudaGetSymbolAddress((void**)&H1, g_H1);
    cudaGetSymbolAddress((void**)&X2, g_X2);
    cudaGetSymbolAddress((void**)&H2, g_H2);

    const int F1_SMEM = (64 * 132 + 64 * 132) * 4;
    const int F2_SMEM = (64 * 132 + 64 * 68) * 4;
    // attn smem: BM*DP + BN*DP + D*68 + BM*68 + 3*BM  floats
    const int A1_SMEM = (128 * 132 + 64 * 132 + 128 * 68 + 128 * 68 + 3 * 128) * 4; // 172544
    const int A2_SMEM = (128 * 68 + 64 * 68 + 64 * 68 + 128 * 68 + 3 * 128) * 4;    // 105984

    cudaFuncSetAttribute(feat_kernel<64, 128>, cudaFuncAttributeMaxDynamicSharedMemorySize, F1_SMEM);
    cudaFuncSetAttribute(feat_kernel<1024, 64>, cudaFuncAttributeMaxDynamicSharedMemorySize, F2_SMEM);
    cudaFuncSetAttribute(attn_tc<128>, cudaFuncAttributeMaxDynamicSharedMemorySize, A1_SMEM);
    cudaFuncSetAttribute(attn_tc<64>, cudaFuncAttributeMaxDynamicSharedMemorySize, A2_SMEM);

    feat_kernel<64, 128><<<dim3(128, 8), 256, F1_SMEM>>>(x, Wh, H1);
    attn_tc<128><<<dim3(8, 16, 8), 256, A1_SMEM>>>(H1, graph, bh, X2, 1024);
    feat_kernel<1024, 64><<<dim3(128, 1), 256, F2_SMEM>>>(X2, W_out, H2);
    attn_tc<64><<<dim3(8, 16, 1), 256, A2_SMEM>>>(H2, graph, b_out, out, 64);
}

// round 16
// speedup vs baseline: 1.2827x; 1.0843x over previous
#include <cuda_runtime.h>
#include <cstdint>

// GATNet on GB300: attention on tensor cores via 3xTF32 mma.sync, v3.
// v3: 512 threads (16 warps -> 4/SMSP), register-prefetched K/V chunk + graph
//     tile (hides GMEM latency), no VT copy (16-way-conflict transpose stores
//     removed), conflict-free softmax interleave, 3 barriers/chunk.
// B=16, N=1024, CIN=64, D=128, H=8, COUT=64

#define LOG2E 1.4426950408889634f
static const int NV = 1024, BV = 16, DHD = 128, NHV = 8, COUT = 64;

__device__ float g_H1[(size_t)NHV * BV * NV * DHD];   // 67 MB
__device__ float g_X2[(size_t)BV * NV * (NHV * DHD)]; // 64 MB
__device__ float g_H2[(size_t)BV * NV * COUT];        // 4 MB

__device__ __forceinline__ float to_tf32(float x) {
    unsigned u;
    asm("cvt.rna.tf32.f32 %0, %1;" : "=r"(u) : "f"(x));
    return __uint_as_float(u);
}
__device__ __forceinline__ void split2(float v, float& h, float& l) {
    h = to_tf32(v);
    l = to_tf32(v - h);
}
__device__ __forceinline__ void mma8(float* d, const float* a, const float* b) {
    asm volatile(
        "mma.sync.aligned.m16n8k8.row.col.f32.tf32.tf32.f32 "
        "{%0,%1,%2,%3}, {%4,%5,%6,%7}, {%8,%9}, {%0,%1,%2,%3};"
        : "+f"(d[0]), "+f"(d[1]), "+f"(d[2]), "+f"(d[3])
        : "r"(__float_as_uint(a[0])), "r"(__float_as_uint(a[1])),
          "r"(__float_as_uint(a[2])), "r"(__float_as_uint(a[3])),
          "r"(__float_as_uint(b[0])), "r"(__float_as_uint(b[1])));
}

// ---------------------------------------------------------------------------
// Unified fp32 feature GEMM (unchanged from passing R11/R15 kernel).
// ---------------------------------------------------------------------------
template <int KTOT, int NC>
__global__ __launch_bounds__(256, 1)
void feat_kernel(const float* __restrict__ x, const float* __restrict__ Wall,
                 float* __restrict__ outp)
{
    const int BMP = 132, NCP = NC + 4;
    constexpr int U = NC / 16;
    extern __shared__ float sm[];
    float* Xs = sm;
    float* Ws = sm + 64 * BMP;

    int tid = threadIdx.x, tx = tid & 15, ty = tid >> 4;
    int rowbase = blockIdx.x * 128;
    const float* W = Wall + (size_t)blockIdx.y * KTOT * NC;

    float acc[8][U];
#pragma unroll
    for (int r = 0; r < 8; r++)
#pragma unroll
        for (int u = 0; u < U; u++) acc[r][u] = 0.0f;

    for (int kc = 0; kc < KTOT / 64; kc++) {
        __syncthreads();
        for (int idx = tid; idx < 128 * 16; idx += 256) {
            int row = idx >> 4, c4 = idx & 15;
            float4 v = *(const float4*)(x + (size_t)(rowbase + row) * KTOT + kc * 64 + c4 * 4);
            Xs[(c4 * 4 + 0) * BMP + row] = v.x;
            Xs[(c4 * 4 + 1) * BMP + row] = v.y;
            Xs[(c4 * 4 + 2) * BMP + row] = v.z;
            Xs[(c4 * 4 + 3) * BMP + row] = v.w;
        }
        for (int idx = tid; idx < 64 * (NC / 4); idx += 256) {
            int k = idx / (NC / 4), c4 = idx % (NC / 4);
            *(float4*)&Ws[k * NCP + c4 * 4] =
                *(const float4*)(W + (size_t)(kc * 64 + k) * NC + c4 * 4);
        }
        __syncthreads();
#pragma unroll 4
        for (int k = 0; k < 64; k++) {
            float4 a0 = *(const float4*)&Xs[k * BMP + ty * 8];
            float4 a1 = *(const float4*)&Xs[k * BMP + ty * 8 + 4];
            float a[8] = {a0.x, a0.y, a0.z, a0.w, a1.x, a1.y, a1.z, a1.w};
            float b[U];
#pragma unroll
            for (int u = 0; u < U; u++) b[u] = Ws[k * NCP + tx + 16 * u];
#pragma unroll
            for (int r = 0; r < 8; r++)
#pragma unroll
                for (int u = 0; u < U; u++) acc[r][u] += a[r] * b[u];
        }
    }
#pragma unroll
    for (int r = 0; r < 8; r++) {
        size_t ro = ((size_t)blockIdx.y * 16384 + rowbase + ty * 8 + r) * NC;
#pragma unroll
        for (int u = 0; u < U; u++) outp[ro + tx + 16 * u] = acc[r][u];
    }
}

// ---------------------------------------------------------------------------
// Tensor-core masked flash attention v3.
// grid (N/128, B, heads), 512 thr = 16 warps = 8 M-groups (16 rows) x 2 N-halves.
// smem: QF[128][D+4], KF[64][D+4] (K and V), PF[128][68], MR/LR/AL[128].
// ---------------------------------------------------------------------------
template <int D>
__global__ __launch_bounds__(512, 1)
void attn_tc(const float* __restrict__ Hf, const float* __restrict__ graph,
             const float* __restrict__ bias, float* __restrict__ out,
             int out_stride)
{
    constexpr int BM = 128, BN = 64, DP = D + 4, NN = 1024;
    constexpr int NO = D / 16;              // n8 O-frags per warp (D/2 cols)
    constexpr int NL = (BN * (D / 4)) / 512; // float4 per thread per chunk
    extern __shared__ float sm[];
    float* QF = sm;                  // BM*DP
    float* KF = QF + BM * DP;        // BN*DP  (K and V, natural layout)
    float* PF = KF + BN * DP;        // BM*68  raw scores -> p
    float* MR = PF + BM * 68;        // BM
    float* LR = MR + BM;             // BM
    float* AL = LR + BM;             // BM

    int tid = threadIdx.x, lane = tid & 31, wid = tid >> 5;
    int wm = wid >> 1, wn = wid & 1;
    int g = lane >> 2, t4 = lane & 3;
    int z = blockIdx.z, bb = blockIdx.y, qbase = blockIdx.x * BM;
    const float* Hp = Hf + (size_t)(z * gridDim.y + bb) * NN * D;

    const int R = wm * 16, C = wn * 32, CD = wn * (D / 2);
    const int ra = R + g, rb = R + 8 + g;

    // load Q tile (plain fp32)
    for (int idx = tid; idx < BM * (D / 4); idx += 512) {
        int r = idx / (D / 4), c4 = idx % (D / 4);
        *(float4*)&QF[r * DP + c4 * 4] =
            *(const float4*)(Hp + (size_t)(qbase + r) * D + c4 * 4);
    }
    if (tid < BM) { MR[tid] = -3.0e38f; LR[tid] = 0.0f; }

    // prefetch chunk 0 into registers
    float4 hbuf[NL];
#pragma unroll
    for (int j = 0; j < NL; j++) {
        int i = j * 512 + tid;
        int r = i / (D / 4), c4 = i % (D / 4);
        hbuf[j] = *(const float4*)(Hp + (size_t)r * D + c4 * 4);
    }

    float O[NO][4];
#pragma unroll
    for (int n = 0; n < NO; n++)
#pragma unroll
        for (int i = 0; i < 4; i++) O[n][i] = 0.0f;

    for (int ch = 0; ch < NN / BN; ch++) {
        int kb = ch * BN;
        __syncthreads();   // KF/PF free from previous iteration
        // commit prefetched chunk to smem
#pragma unroll
        for (int j = 0; j < NL; j++) {
            int i = j * 512 + tid;
            int r = i / (D / 4), c4 = i % (D / 4);
            *(float4*)&KF[r * DP + c4 * 4] = hbuf[j];
        }
        // prefetch NEXT chunk (in flight through the whole body)
        if (ch + 1 < NN / BN) {
#pragma unroll
            for (int j = 0; j < NL; j++) {
                int i = j * 512 + tid;
                int r = i / (D / 4), c4 = i % (D / 4);
                hbuf[j] = *(const float4*)(Hp + (size_t)(kb + BN + r) * D + c4 * 4);
            }
        }
        // prefetch graph values for THIS chunk (consumed after scores)
        float garr[16];
        {
            const float* gra = graph + (size_t)(qbase + ra) * NN + kb;
            const float* grb = graph + (size_t)(qbase + rb) * NN + kb;
#pragma unroll
            for (int f = 0; f < 4; f++) {
                int n0 = C + f * 8 + 2 * t4;
                garr[f * 4 + 0] = gra[n0];
                garr[f * 4 + 1] = gra[n0 + 1];
                garr[f * 4 + 2] = grb[n0];
                garr[f * 4 + 3] = grb[n0 + 1];
            }
        }
        __syncthreads();   // KF visible

        // ---- scores: warp tile 16x32 = 4 n8 frags, 3-term split ----
        float S[4][4];
#pragma unroll
        for (int f = 0; f < 4; f++)
#pragma unroll
            for (int i = 0; i < 4; i++) S[f][i] = 0.0f;

#pragma unroll
        for (int k = 0; k < D; k += 8) {
            float ah[4], al_[4];
            split2(QF[ra * DP + k + t4],     ah[0], al_[0]);
            split2(QF[rb * DP + k + t4],     ah[1], al_[1]);
            split2(QF[ra * DP + k + 4 + t4], ah[2], al_[2]);
            split2(QF[rb * DP + k + 4 + t4], ah[3], al_[3]);
#pragma unroll
            for (int f = 0; f < 4; f++) {
                int nb = C + f * 8 + g;
                float bh[2], bl[2];
                split2(KF[nb * DP + k + t4],     bh[0], bl[0]);
                split2(KF[nb * DP + k + 4 + t4], bh[1], bl[1]);
                mma8(S[f], ah, bh);
                mma8(S[f], ah, bl);
                mma8(S[f], al_, bh);
            }
        }

        // mask (s*graph; s==0 -> -1e16) using prefetched garr, stage to PF
#pragma unroll
        for (int f = 0; f < 4; f++) {
            int n0 = C + f * 8 + 2 * t4;
            float s;
            s = S[f][0] * garr[f * 4 + 0]; PF[ra * 68 + n0]     = (s == 0.0f) ? -1e16f : s;
            s = S[f][1] * garr[f * 4 + 1]; PF[ra * 68 + n0 + 1] = (s == 0.0f) ? -1e16f : s;
            s = S[f][2] * garr[f * 4 + 2]; PF[rb * 68 + n0]     = (s == 0.0f) ? -1e16f : s;
            s = S[f][3] * garr[f * 4 + 3]; PF[rb * 68 + n0 + 1] = (s == 0.0f) ? -1e16f : s;
        }
        __syncthreads();

        // ---- online softmax: 16 warps x 8 rows; interleaved cols t4+4c
        //      (bank = 4g + t4 + 4c -> conflict-free) ----
        {
            int row = wid * 8 + g;
            float* pr = PF + row * 68 + t4;
            float mx = -3.0e38f;
#pragma unroll
            for (int c = 0; c < 16; c++) mx = fmaxf(mx, pr[4 * c]);
            mx = fmaxf(mx, __shfl_xor_sync(0xffffffffu, mx, 1));
            mx = fmaxf(mx, __shfl_xor_sync(0xffffffffu, mx, 2));
            float mold = MR[row];
            float mnew = fmaxf(mold, mx);
            float rs = 0.0f;
#pragma unroll
            for (int c = 0; c < 16; c++) {
                float p = exp2f((pr[4 * c] - mnew) * LOG2E);
                rs += p;
                pr[4 * c] = p;
            }
            rs += __shfl_xor_sync(0xffffffffu, rs, 1);
            rs += __shfl_xor_sync(0xffffffffu, rs, 2);
            if (t4 == 0) {
                float a = exp2f((mold - mnew) * LOG2E);
                MR[row] = mnew;
                LR[row] = LR[row] * a + rs;
                AL[row] = a;
            }
        }
        __syncthreads();

        // ---- rescale O, then O += P @ V (warp tile 16 x D/2) ----
        {
            float a0 = AL[ra], a1 = AL[rb];
#pragma unroll
            for (int n = 0; n < NO; n++) {
                O[n][0] *= a0; O[n][1] *= a0;
                O[n][2] *= a1; O[n][3] *= a1;
            }
        }
#pragma unroll
        for (int kk = 0; kk < BN; kk += 8) {
            float ph[4], pl[4];
            split2(PF[ra * 68 + kk + t4],     ph[0], pl[0]);
            split2(PF[rb * 68 + kk + t4],     ph[1], pl[1]);
            split2(PF[ra * 68 + kk + 4 + t4], ph[2], pl[2]);
            split2(PF[rb * 68 + kk + 4 + t4], ph[3], pl[3]);
#pragma unroll
            for (int n = 0; n < NO; n++) {
                int dc = CD + n * 8 + g;
                float vh[2], vl[2];
                split2(KF[(kk + t4) * DP + dc],     vh[0], vl[0]);
                split2(KF[(kk + 4 + t4) * DP + dc], vh[1], vl[1]);
                mma8(O[n], ph, vh);
                mma8(O[n], ph, vl);
                mma8(O[n], pl, vh);
            }
        }
    }

    // ---- epilogue: /l, +bias, leaky relu, store ----
    const float* bi = bias + (size_t)z * D;
    float* op = out + (size_t)bb * NN * out_stride + (size_t)z * D;
    float inva = 1.0f / LR[ra], invb = 1.0f / LR[rb];
#pragma unroll
    for (int n = 0; n < NO; n++) {
        int d0 = CD + n * 8 + 2 * t4;
        float b0 = bi[d0], b1 = bi[d0 + 1];
        float v;
        v = O[n][0] * inva + b0; v = v > 0.0f ? v : 0.01f * v;
        op[(size_t)(qbase + ra) * out_stride + d0] = v;
        v = O[n][1] * inva + b1; v = v > 0.0f ? v : 0.01f * v;
        op[(size_t)(qbase + ra) * out_stride + d0 + 1] = v;
        v = O[n][2] * invb + b0; v = v > 0.0f ? v : 0.01f * v;
        op[(size_t)(qbase + rb) * out_stride + d0] = v;
        v = O[n][3] * invb + b1; v = v > 0.0f ? v : 0.01f * v;
        op[(size_t)(qbase + rb) * out_stride + d0 + 1] = v;
    }
}

// ---------------------------------------------------------------------------
extern "C" void kernel_launch(void* const* d_in, const int* in_sizes, int n_in,
                              void* d_out, int out_size)
{
    const float* x     = (const float*)d_in[0];
    const float* graph = (const float*)d_in[1];
    const float* Wh    = (const float*)d_in[2];
    const float* bh    = (const float*)d_in[3];
    const float* W_out = (const float*)d_in[4];
    const float* b_out = (const float*)d_in[5];
    float* out = (float*)d_out;

    float *H1, *X2, *H2;
    cudaGetSymbolAddress((void**)&H1, g_H1);
    cudaGetSymbolAddress((void**)&X2, g_X2);
    cudaGetSymbolAddress((void**)&H2, g_H2);

    const int F1_SMEM = (64 * 132 + 64 * 132) * 4;
    const int F2_SMEM = (64 * 132 + 64 * 68) * 4;
    // attn smem: BM*DP + BN*DP + BM*68 + 3*BM floats
    const int A1_SMEM = (128 * 132 + 64 * 132 + 128 * 68 + 3 * 128) * 4; // 137728
    const int A2_SMEM = (128 * 68 + 64 * 68 + 128 * 68 + 3 * 128) * 4;   // 88576

    cudaFuncSetAttribute(feat_kernel<64, 128>, cudaFuncAttributeMaxDynamicSharedMemorySize, F1_SMEM);
    cudaFuncSetAttribute(feat_kernel<1024, 64>, cudaFuncAttributeMaxDynamicSharedMemorySize, F2_SMEM);
    cudaFuncSetAttribute(attn_tc<128>, cudaFuncAttributeMaxDynamicSharedMemorySize, A1_SMEM);
    cudaFuncSetAttribute(attn_tc<64>, cudaFuncAttributeMaxDynamicSharedMemorySize, A2_SMEM);

    feat_kernel<64, 128><<<dim3(128, 8), 256, F1_SMEM>>>(x, Wh, H1);
    attn_tc<128><<<dim3(8, 16, 8), 512, A1_SMEM>>>(H1, graph, bh, X2, 1024);
    feat_kernel<1024, 64><<<dim3(128, 1), 256, F2_SMEM>>>(X2, W_out, H2);
    attn_tc<64><<<dim3(8, 16, 1), 512, A2_SMEM>>>(H2, graph, b_out, out, 64);
}